// round 6
// baseline (speedup 1.0000x reference)
#include <cuda_runtime.h>
#include <cstdint>
#include <cstddef>

#define Bv     8
#define Nv     128
#define FNv    64
#define IPC    8
#define CHUNKS 16

// ------------------------------ device scratch ------------------------------
// B operand [n=2l+br (128)][k' (128)+pad4], tf32 bits, k-permuted within 8-groups:
// stored pos p in group: p=2o for o<4, p=2(o-4)+1 -> (k0+tg, k0+tg+4) adjacent.
// k<64 -> We rows (W[128+k]); 64<=k<128 -> Wj rows (W[k]).
__device__ float g_Wt[128 * 132];
__device__ float g_part[Bv * CHUNKS * Nv * FNv];

// ------------------------------ helpers ------------------------------
__device__ __forceinline__ uint32_t cvt_tf32(float x) {
    uint32_t r; asm("cvt.rna.tf32.f32 %0, %1;" : "=r"(r) : "f"(x)); return r;
}
__device__ __forceinline__ uint32_t smem_u32(const void* p) {
    uint32_t a;
    asm("{ .reg .u64 t; cvta.to.shared.u64 t, %1; cvt.u32.u64 %0, t; }" : "=r"(a) : "l"(p));
    return a;
}
__device__ __forceinline__ void cp16(uint32_t dst, const void* src) {
    asm volatile("cp.async.cg.shared.global [%0], [%1], 16;" :: "r"(dst), "l"(src) : "memory");
}
__device__ __forceinline__ void cp_commit() {
    asm volatile("cp.async.commit_group;" ::: "memory");
}
template <int N>
__device__ __forceinline__ void cp_wait() {
    asm volatile("cp.async.wait_group %0;" :: "n"(N) : "memory");
}
__device__ __forceinline__ void mma8(float* c, const uint32_t* a, uint32_t b0, uint32_t b1) {
    asm volatile(
        "mma.sync.aligned.m16n8k8.row.col.f32.tf32.tf32.f32 "
        "{%0,%1,%2,%3}, {%4,%5,%6,%7}, {%8,%9}, {%0,%1,%2,%3};"
        : "+f"(c[0]), "+f"(c[1]), "+f"(c[2]), "+f"(c[3])
        : "r"(a[0]), "r"(a[1]), "r"(a[2]), "r"(a[3]), "r"(b0), "r"(b1));
}

// ------------------------------ weight prep ------------------------------
__global__ void __launch_bounds__(256)
wprep_kernel(const float* __restrict__ Watt, const float* __restrict__ Wnei) {
    const int idx = blockIdx.x * 256 + threadIdx.x;      // < 16896 = 66*256
    const int n = idx / 132, kp = idx % 132;
    const int l = n >> 1, br = n & 1;
    float val = 0.f;
    if (kp < 128) {
        const int ks = kp >> 3, p = kp & 7;
        const int o = (p >> 1) + ((p & 1) << 2);         // inverse of perm
        const int k = ks * 8 + o;
        const float* __restrict__ W = br ? Wnei : Watt;
        const int row = (k < 64) ? (128 + k) : k;
        val = W[row * 64 + l];
    }
    g_Wt[idx] = __uint_as_float(cvt_tf32(val));
}

// ------------------------------ main kernel ------------------------------
#define EROW    68
#define WROW    132
#define OFF_W   0            // 64 rows x 528 B = 33792
#define OFF_E   33792        // 128 x 272 B = 34816 (H tile pre-loop, then E tiles)
#define OFF_PI  68608        // 8 ii x 32 lloc x float2 = 2048
#define OFF_A   70656        // 8 ii x 128 j x 4 = 4096
#define OFF_BS  74752        // 32 lloc x float2 = 256
#define SMEM_DYN 75008

__global__ void __launch_bounds__(256, 2)
main_kernel(const float* __restrict__ A,
            const float* __restrict__ E,
            const float* __restrict__ H,
            const float* __restrict__ Watt,
            const float* __restrict__ Wnei,
            const float* __restrict__ biasA,
            const float* __restrict__ biasN) {
    extern __shared__ char sm[];
    const uint32_t sb = smem_u32(sm);

    const int t = threadIdx.x, lane = t & 31, wid = t >> 5;
    const int g = lane >> 2, tg = lane & 3;
    const int b     = blockIdx.x >> 5;
    const int chunk = (blockIdx.x >> 1) & 15;
    const int lhalf = blockIdx.x & 1;
    const int i0    = chunk * IPC;
    const int jw    = wid * 16;                 // warp's 16-row j slice

    // ---- prologue loads: W slice + H tile + A chunk ----
    {
        const char* Wg = (const char*)g_Wt + (size_t)lhalf * 33792;
        #pragma unroll
        for (int v = 0; v < 9; v++) {
            const int n = v * 256 + t;
            if (n < 2112) cp16(sb + OFF_W + n * 16, Wg + n * 16);
        }
        const char* Hg = (const char*)(H + (size_t)b * Nv * FNv);
        #pragma unroll
        for (int v = 0; v < 8; v++) {
            const int n = v * 256 + t, row = n >> 4, c = n & 15;
            cp16(sb + OFF_E + row * 272 + c * 16, Hg + n * 16);
        }
        cp16(sb + OFF_A + t * 16, (const char*)(A + (size_t)(b * Nv + i0) * Nv) + t * 16);
        cp_commit();
    }
    if (t < 32) {
        const int lg = lhalf * 32 + t;
        ((float2*)(sm + OFF_BS))[t] = make_float2(__ldg(biasA + lg), __ldg(biasN + lg));
    }
    cp_wait<0>();
    __syncthreads();

    const float*    __restrict__ Hb = (const float*)(sm + OFF_E);
    const uint32_t* __restrict__ Wb = (const uint32_t*)(sm + OFF_W);

    // ---- Pj GEMM into registers: pj[nt] = {att(g), nei(g), att(g+8), nei(g+8)} ----
    float pj[8][4];
    #pragma unroll
    for (int nt = 0; nt < 8; nt++)
        #pragma unroll
        for (int q = 0; q < 4; q++) pj[nt][q] = 0.f;
    #pragma unroll
    for (int ks = 0; ks < 8; ks++) {
        const int k0 = ks * 8;
        const float* ap = Hb + (jw + g) * EROW + k0 + tg;
        uint32_t a[4];
        a[0] = cvt_tf32(ap[0]);
        a[1] = cvt_tf32(ap[8 * EROW]);
        a[2] = cvt_tf32(ap[4]);
        a[3] = cvt_tf32(ap[8 * EROW + 4]);
        #pragma unroll
        for (int nt = 0; nt < 8; nt++) {
            const uint2 bu = *(const uint2*)(Wb + (nt * 8 + g) * WROW + 64 + k0 + tg * 2);
            mma8(pj[nt], a, bu.x, bu.y);
        }
    }
    // ---- Pi (warp wid -> ii=wid; lane -> lloc) ----
    {
        const float* __restrict__ Hrow = Hb + (i0 + wid) * EROW;
        const int lg = lhalf * 32 + lane;
        float aA = 0.f, aN = 0.f;
        #pragma unroll 8
        for (int f = 0; f < 64; f++) {
            const float h = Hrow[f];
            aA = fmaf(h, __ldg(Watt + f * 64 + lg), aA);
            aN = fmaf(h, __ldg(Wnei + f * 64 + lg), aN);
        }
        ((float2*)(sm + OFF_PI))[wid * 32 + lane] = make_float2(aA, aN);
    }
    __syncthreads();   // H reads done -> E tile 0 may overwrite

    // ---- E tile 0 ----
    {
        const char* Eg = (const char*)(E + ((size_t)(b * Nv + i0)) * Nv * FNv);
        #pragma unroll
        for (int v = 0; v < 8; v++) {
            const int n = v * 256 + t, row = n >> 4, c = n & 15;
            cp16(sb + OFF_E + row * 272 + c * 16, Eg + n * 16);
        }
        cp_commit();
    }

    float outacc[2][8];
    #pragma unroll
    for (int h = 0; h < 2; h++)
        #pragma unroll
        for (int nt = 0; nt < 8; nt++) outacc[h][nt] = 0.f;

    for (int ii = 0; ii < IPC; ii++) {
        cp_wait<0>();
        __syncthreads();                         // tile ii visible everywhere

        float c[8][4];
        #pragma unroll
        for (int nt = 0; nt < 8; nt++)
            #pragma unroll
            for (int q = 0; q < 4; q++) c[nt][q] = 0.f;

        #pragma unroll
        for (int ks = 0; ks < 8; ks++) {
            const int k0 = ks * 8;
            const float* ap = Hb + (jw + g) * EROW + k0 + tg;   // Hb == E buffer base
            uint32_t a[4];
            a[0] = cvt_tf32(ap[0]);
            a[1] = cvt_tf32(ap[8 * EROW]);
            a[2] = cvt_tf32(ap[4]);
            a[3] = cvt_tf32(ap[8 * EROW + 4]);
            #pragma unroll
            for (int nt = 0; nt < 8; nt++) {
                const uint2 bu = *(const uint2*)(Wb + (nt * 8 + g) * WROW + k0 + tg * 2);
                mma8(c[nt], a, bu.x, bu.y);
            }
        }
        __syncthreads();                         // all reads of tile ii done

        if (ii + 1 < IPC) {                      // next tile streams under epilogue
            const char* Eg = (const char*)(E + ((size_t)(b * Nv + i0 + ii + 1)) * Nv * FNv);
            #pragma unroll
            for (int v = 0; v < 8; v++) {
                const int n = v * 256 + t, row = n >> 4, c2 = n & 15;
                cp16(sb + OFF_E + row * 272 + c2 * 16, Eg + n * 16);
            }
            cp_commit();
        }

        // ---- epilogue ----
        const float*  __restrict__ As  = (const float*)(sm + OFF_A) + ii * 128;
        const float2* __restrict__ Pis = (const float2*)(sm + OFF_PI) + ii * 32;
        const float2* __restrict__ Bs  = (const float2*)(sm + OFF_BS);
        const float a0 = As[jw + g], a1 = As[jw + g + 8];
        #pragma unroll
        for (int nt = 0; nt < 8; nt++) {
            const int lloc = nt * 4 + tg;
            const float2 pi = Pis[lloc];
            const float2 bs = Bs[lloc];
            {
                const float att = fmaf(a0, c[nt][0] + pi.x + pj[nt][0], bs.x);
                const float cv  = fmaf(a0, c[nt][1] + pi.y + pj[nt][1], bs.y);
                float th; asm("tanh.approx.f32 %0, %1;" : "=f"(th) : "f"(att * 0.5f));
                outacc[0][nt] = fmaf(fmaxf(cv, 0.f), fmaf(0.5f, th, 0.5f), outacc[0][nt]);
            }
            {
                const float att = fmaf(a1, c[nt][2] + pi.x + pj[nt][2], bs.x);
                const float cv  = fmaf(a1, c[nt][3] + pi.y + pj[nt][3], bs.y);
                float th; asm("tanh.approx.f32 %0, %1;" : "=f"(th) : "f"(att * 0.5f));
                outacc[1][nt] = fmaf(fmaxf(cv, 0.f), fmaf(0.5f, th, 0.5f), outacc[1][nt]);
            }
        }
    }

    // ---- store partials ----
    float* __restrict__ dst = g_part + ((size_t)(b * CHUNKS + chunk) * Nv) * FNv
                            + lhalf * 32;
    #pragma unroll
    for (int h = 0; h < 2; h++) {
        const int j = jw + h * 8 + g;
        #pragma unroll
        for (int nt = 0; nt < 8; nt++)
            dst[(size_t)j * FNv + nt * 4 + tg] = outacc[h][nt];
    }
}

// ------------------------------ reduce kernel ------------------------------
__global__ void __launch_bounds__(256)
reduce_kernel(float* __restrict__ out) {
    const int f4 = blockIdx.x * 256 + threadIdx.x;
    const int b = f4 >> 11;
    const int r = f4 & 2047;
    const float4* P = (const float4*)g_part;
    float4 s = make_float4(0.f, 0.f, 0.f, 0.f);
    #pragma unroll
    for (int c = 0; c < CHUNKS; c++) {
        const float4 v = P[((size_t)(b * CHUNKS + c)) * 2048 + r];
        s.x += v.x; s.y += v.y; s.z += v.z; s.w += v.w;
    }
    ((float4*)out)[b * 2048 + r] = s;
}

// ------------------------------ launch ------------------------------
extern "C" void kernel_launch(void* const* d_in, const int* in_sizes, int n_in,
                              void* d_out, int out_size) {
    const float* H    = (const float*)d_in[0];
    const float* A    = (const float*)d_in[1];
    const float* E    = (const float*)d_in[2];
    const float* Watt = (const float*)d_in[3];
    const float* Wnei = (const float*)d_in[4];
    const float* bAtt = (const float*)d_in[5];
    const float* bNei = (const float*)d_in[6];
    float* out = (float*)d_out;

    cudaFuncSetAttribute(main_kernel, cudaFuncAttributeMaxDynamicSharedMemorySize, SMEM_DYN);

    wprep_kernel<<<66, 256>>>(Watt, Wnei);
    main_kernel<<<Bv * CHUNKS * 2, 256, SMEM_DYN>>>(A, E, H, Watt, Wnei, bAtt, bNei);
    reduce_kernel<<<64, 256>>>(out);
}

// round 7
// speedup vs baseline: 1.5925x; 1.5925x over previous
#include <cuda_runtime.h>
#include <cuda_fp16.h>
#include <cstdint>
#include <cstddef>

#define Bv     8
#define Nv     128
#define FNv    64
#define IPC    8
#define CHUNKS 16

// ------------------------------ device scratch ------------------------------
// fp16 B operand: [n=2l+br (128 rows)][kp (192 perm + pad16)] halves, row = 208 halves.
// k-groups of 16 permuted so (2tg,2tg+1,2tg+8,2tg+9) are contiguous (one LDS.64).
// ks 0..3 = We rows (W[128+k]), ks 4..7 = Wj rows (W[k]), ks 8..11 = Wi rows (W[k-128]).
__device__ unsigned short g_Wh[128 * 208];
__device__ float g_part[Bv * CHUNKS * Nv * FNv];

// ------------------------------ helpers ------------------------------
__device__ __forceinline__ uint32_t smem_u32(const void* p) {
    uint32_t a;
    asm("{ .reg .u64 t; cvta.to.shared.u64 t, %1; cvt.u32.u64 %0, t; }" : "=r"(a) : "l"(p));
    return a;
}
__device__ __forceinline__ void cp16(uint32_t dst, const void* src) {
    asm volatile("cp.async.cg.shared.global [%0], [%1], 16;" :: "r"(dst), "l"(src) : "memory");
}
__device__ __forceinline__ void cp_commit() {
    asm volatile("cp.async.commit_group;" ::: "memory");
}
template <int N>
__device__ __forceinline__ void cp_wait() {
    asm volatile("cp.async.wait_group %0;" :: "n"(N) : "memory");
}
__device__ __forceinline__ uint32_t packh2(float lo, float hi) {
    uint32_t d; asm("cvt.rn.f16x2.f32 %0, %1, %2;" : "=r"(d) : "f"(hi), "f"(lo)); return d;
}
__device__ __forceinline__ void mma16(float* c, const uint32_t* a, uint32_t b0, uint32_t b1) {
    asm volatile(
        "mma.sync.aligned.m16n8k16.row.col.f32.f16.f16.f32 "
        "{%0,%1,%2,%3}, {%4,%5,%6,%7}, {%8,%9}, {%0,%1,%2,%3};"
        : "+f"(c[0]), "+f"(c[1]), "+f"(c[2]), "+f"(c[3])
        : "r"(a[0]), "r"(a[1]), "r"(a[2]), "r"(a[3]), "r"(b0), "r"(b1));
}

// ------------------------------ weight prep ------------------------------
__global__ void __launch_bounds__(256)
wprep_kernel(const float* __restrict__ Watt, const float* __restrict__ Wnei) {
    const int idx = blockIdx.x * 256 + threadIdx.x;   // < 26624 = 104*256
    const int n = idx / 208, kp = idx % 208;
    const int l = n >> 1, br = n & 1;
    float val = 0.f;
    if (kp < 192) {
        const int ks = kp >> 4, p16 = kp & 15;
        const int k16 = ((p16 >> 2) * 2) + (p16 & 1) + ((p16 >> 1) & 1) * 8;
        const int kglob = ks * 16 + k16;
        int row;
        if (ks < 4)      row = 128 + kglob;     // We
        else if (ks < 8) row = kglob;           // Wj (rows 64..127)
        else             row = kglob - 128;     // Wi (rows 0..63)
        const float* __restrict__ W = br ? Wnei : Watt;
        val = W[row * 64 + l];
    }
    g_Wh[idx] = __half_as_ushort(__float2half_rn(val));
}

// ------------------------------ main kernel ------------------------------
#define OFF_WH  0            // 128 x 416 B = 53248
#define OFF_E16 53248        // 2 x (128 x 160 B) = 40960
#define E16BUF  20480
#define OFF_PJ  94208        // 128 x 68 float2 = 69632
#define PJW     68
#define OFF_PI  163840       // 8 ii x 64 l float2 = 4096
#define OFF_A   167936       // 8 ii x 128 j fp32 = 4096
#define OFF_BS  172032       // 64 float2 = 512
#define SMEM_DYN 172544

__global__ void __launch_bounds__(256, 1)
main_kernel(const float* __restrict__ A,
            const float* __restrict__ E,
            const float* __restrict__ H,
            const float* __restrict__ biasA,
            const float* __restrict__ biasN) {
    extern __shared__ char sm[];
    const uint32_t sb = smem_u32(sm);

    const int t = threadIdx.x, lane = t & 31, wid = t >> 5;
    const int g = lane >> 2, tg = lane & 3;
    const int b = blockIdx.x >> 4, chunk = blockIdx.x & 15, i0 = chunk * IPC;
    const int mbase = (wid & 3) * 32;
    const int wn    = wid >> 2;
    const int lbase = wn * 32;
    const int nrow0 = wn * 64;

    const uint32_t* __restrict__ Ww = (const uint32_t*)(sm + OFF_WH);

    // ---- async loads: W' + A chunk ----
    {
        #pragma unroll
        for (int v = 0; v < 13; v++)
            cp16(sb + OFF_WH + (v * 256 + t) * 16, (const char*)g_Wh + (v * 256 + t) * 16);
        cp16(sb + OFF_A + t * 16, (const char*)(A + (size_t)(b * Nv + i0) * Nv) + t * 16);
        cp_commit();
    }
    // ---- H tile: LDG -> fp16 permuted STS into E16 buf0 ----
    {
        const float4* Hg = (const float4*)(H + (size_t)b * Nv * FNv);
        float4 hl[8];
        #pragma unroll
        for (int v = 0; v < 8; v++) hl[v] = Hg[v * 256 + t];
        uint32_t* Ebw = (uint32_t*)(sm + OFF_E16);
        #pragma unroll
        for (int v = 0; v < 8; v++) {
            const int n = v * 256 + t, row = n >> 4, kgf = n & 15;
            const int wbase = row * 40 + (kgf >> 2) * 8 + ((kgf & 1) * 4) + ((kgf >> 1) & 1);
            Ebw[wbase]     = packh2(hl[v].x, hl[v].y);
            Ebw[wbase + 2] = packh2(hl[v].z, hl[v].w);
        }
    }
    if (t < 64)
        ((float2*)(sm + OFF_BS))[t] = make_float2(__ldg(biasA + t), __ldg(biasN + t));
    cp_wait<0>();
    __syncthreads();          // W + A + H-tile resident

    // ---- prologue GEMM: Pj (ks 4..7) and Pi (ks 8..11) from H ----
    {
        const uint32_t* __restrict__ Ew = (const uint32_t*)(sm + OFF_E16);
        float cpj[2][8][4], cpi[2][8][4];
        #pragma unroll
        for (int mt = 0; mt < 2; mt++)
            #pragma unroll
            for (int nt = 0; nt < 8; nt++)
                #pragma unroll
                for (int q = 0; q < 4; q++) { cpj[mt][nt][q] = 0.f; cpi[mt][nt][q] = 0.f; }

        #pragma unroll
        for (int ks = 0; ks < 4; ks++) {
            uint32_t a[2][4];
            #pragma unroll
            for (int mt = 0; mt < 2; mt++) {
                const int r = mbase + mt * 16 + g;
                const uint2 u0 = *(const uint2*)(Ew + r * 40 + ks * 8 + tg * 2);
                const uint2 u1 = *(const uint2*)(Ew + (r + 8) * 40 + ks * 8 + tg * 2);
                a[mt][0] = u0.x; a[mt][1] = u1.x; a[mt][2] = u0.y; a[mt][3] = u1.y;
            }
            #pragma unroll
            for (int nt = 0; nt < 8; nt++) {
                const int nr = (nrow0 + nt * 8 + g) * 104;
                const uint2 bj = *(const uint2*)(Ww + nr + (ks + 4) * 8 + tg * 2);
                const uint2 bi = *(const uint2*)(Ww + nr + (ks + 8) * 8 + tg * 2);
                mma16(cpj[0][nt], a[0], bj.x, bj.y);
                mma16(cpj[1][nt], a[1], bj.x, bj.y);
                mma16(cpi[0][nt], a[0], bi.x, bi.y);
                mma16(cpi[1][nt], a[1], bi.x, bi.y);
            }
        }
        // scatter Pj (all threads)
        float2* __restrict__ PJ = (float2*)(sm + OFF_PJ);
        #pragma unroll
        for (int mt = 0; mt < 2; mt++) {
            const int j0 = mbase + mt * 16 + g;
            #pragma unroll
            for (int nt = 0; nt < 8; nt++) {
                const int l = lbase + nt * 4 + tg;
                PJ[(size_t)j0 * PJW + l]       = make_float2(cpj[mt][nt][0], cpj[mt][nt][1]);
                PJ[(size_t)(j0 + 8) * PJW + l] = make_float2(cpj[mt][nt][2], cpj[mt][nt][3]);
            }
        }
        // scatter Pi (owning warp pair only): rows i0..i0+7
        if ((wid & 3) == ((i0 >> 5) & 3)) {
            const int mtv = (i0 >> 4) & 1, hsv = (i0 >> 3) & 1;
            float2* __restrict__ Pis = (float2*)(sm + OFF_PI);
            #pragma unroll
            for (int nt = 0; nt < 8; nt++) {
                float va, vn;
                if (mtv == 0) {
                    if (hsv == 0) { va = cpi[0][nt][0]; vn = cpi[0][nt][1]; }
                    else          { va = cpi[0][nt][2]; vn = cpi[0][nt][3]; }
                } else {
                    if (hsv == 0) { va = cpi[1][nt][0]; vn = cpi[1][nt][1]; }
                    else          { va = cpi[1][nt][2]; vn = cpi[1][nt][3]; }
                }
                Pis[g * 64 + lbase + nt * 4 + tg] = make_float2(va, vn);
            }
        }
    }

    // ---- prefetch E tile 0 ----
    float4 el[8];
    {
        const float4* Eg = (const float4*)(E + ((size_t)(b * Nv + i0)) * Nv * FNv);
        #pragma unroll
        for (int v = 0; v < 8; v++) el[v] = Eg[v * 256 + t];
    }
    __syncthreads();          // Pj/Pi visible; H-tile reads done -> buf0 reusable

    float outacc[2][2][8];
    #pragma unroll
    for (int mt = 0; mt < 2; mt++)
        #pragma unroll
        for (int h = 0; h < 2; h++)
            #pragma unroll
            for (int nt = 0; nt < 8; nt++) outacc[mt][h][nt] = 0.f;

    for (int ii = 0; ii < IPC; ii++) {
        // ---- convert + store tile ii ----
        {
            uint32_t* Ebw = (uint32_t*)(sm + OFF_E16 + (ii & 1) * E16BUF);
            #pragma unroll
            for (int v = 0; v < 8; v++) {
                const int n = v * 256 + t, row = n >> 4, kgf = n & 15;
                const int wbase = row * 40 + (kgf >> 2) * 8 + ((kgf & 1) * 4) + ((kgf >> 1) & 1);
                Ebw[wbase]     = packh2(el[v].x, el[v].y);
                Ebw[wbase + 2] = packh2(el[v].z, el[v].w);
            }
        }
        __syncthreads();

        // ---- prefetch tile ii+1 (lands during GEMM) ----
        if (ii + 1 < IPC) {
            const float4* Eg = (const float4*)(E + ((size_t)(b * Nv + i0 + ii + 1)) * Nv * FNv);
            #pragma unroll
            for (int v = 0; v < 8; v++) el[v] = Eg[v * 256 + t];
        }

        // ---- GEMM (ks 0..3 = We) ----
        const uint32_t* __restrict__ Ew = (const uint32_t*)(sm + OFF_E16 + (ii & 1) * E16BUF);
        float c[2][8][4];
        #pragma unroll
        for (int mt = 0; mt < 2; mt++)
            #pragma unroll
            for (int nt = 0; nt < 8; nt++)
                #pragma unroll
                for (int q = 0; q < 4; q++) c[mt][nt][q] = 0.f;

        #pragma unroll
        for (int ks = 0; ks < 4; ks++) {
            uint32_t a[2][4];
            #pragma unroll
            for (int mt = 0; mt < 2; mt++) {
                const int r = mbase + mt * 16 + g;
                const uint2 u0 = *(const uint2*)(Ew + r * 40 + ks * 8 + tg * 2);
                const uint2 u1 = *(const uint2*)(Ew + (r + 8) * 40 + ks * 8 + tg * 2);
                a[mt][0] = u0.x; a[mt][1] = u1.x; a[mt][2] = u0.y; a[mt][3] = u1.y;
            }
            #pragma unroll
            for (int nt = 0; nt < 8; nt++) {
                const uint2 bu = *(const uint2*)(Ww + (nrow0 + nt * 8 + g) * 104 + ks * 8 + tg * 2);
                mma16(c[0][nt], a[0], bu.x, bu.y);
                mma16(c[1][nt], a[1], bu.x, bu.y);
            }
        }

        // ---- epilogue ----
        const float*  __restrict__ As  = (const float*)(sm + OFF_A) + ii * 128;
        const float2* __restrict__ Pis = (const float2*)(sm + OFF_PI) + ii * 64;
        const float2* __restrict__ Bs  = (const float2*)(sm + OFF_BS);
        const float2* __restrict__ PJ  = (const float2*)(sm + OFF_PJ);

        #pragma unroll
        for (int mt = 0; mt < 2; mt++) {
            const int j0 = mbase + mt * 16 + g;
            const float a0 = As[j0], a1 = As[j0 + 8];
            const float2* pr0 = PJ + (size_t)j0 * PJW;
            const float2* pr1 = PJ + (size_t)(j0 + 8) * PJW;
            #pragma unroll
            for (int nt = 0; nt < 8; nt++) {
                const int l = lbase + nt * 4 + tg;
                const float2 pi = Pis[l];
                const float2 bs = Bs[l];
                const float2 q0 = pr0[l];
                const float2 q1 = pr1[l];
                {
                    const float att = fmaf(a0, c[mt][nt][0] + pi.x + q0.x, bs.x);
                    const float cv  = fmaf(a0, c[mt][nt][1] + pi.y + q0.y, bs.y);
                    float th; asm("tanh.approx.f32 %0, %1;" : "=f"(th) : "f"(att * 0.5f));
                    outacc[mt][0][nt] = fmaf(fmaxf(cv, 0.f), fmaf(0.5f, th, 0.5f),
                                             outacc[mt][0][nt]);
                }
                {
                    const float att = fmaf(a1, c[mt][nt][2] + pi.x + q1.x, bs.x);
                    const float cv  = fmaf(a1, c[mt][nt][3] + pi.y + q1.y, bs.y);
                    float th; asm("tanh.approx.f32 %0, %1;" : "=f"(th) : "f"(att * 0.5f));
                    outacc[mt][1][nt] = fmaf(fmaxf(cv, 0.f), fmaf(0.5f, th, 0.5f),
                                             outacc[mt][1][nt]);
                }
            }
        }
    }

    // ---- store partials ----
    float* __restrict__ dst = g_part + (size_t)blockIdx.x * Nv * FNv;
    #pragma unroll
    for (int mt = 0; mt < 2; mt++)
        #pragma unroll
        for (int h = 0; h < 2; h++) {
            const int j = mbase + mt * 16 + h * 8 + g;
            #pragma unroll
            for (int nt = 0; nt < 8; nt++)
                dst[(size_t)j * FNv + lbase + nt * 4 + tg] = outacc[mt][h][nt];
        }
}

// ------------------------------ reduce kernel ------------------------------
__global__ void __launch_bounds__(256)
reduce_kernel(float* __restrict__ out) {
    const int f4 = blockIdx.x * 256 + threadIdx.x;
    const int b = f4 >> 11;
    const int r = f4 & 2047;
    const float4* P = (const float4*)g_part;
    float4 s = make_float4(0.f, 0.f, 0.f, 0.f);
    #pragma unroll
    for (int c = 0; c < CHUNKS; c++) {
        const float4 v = P[((size_t)(b * CHUNKS + c)) * 2048 + r];
        s.x += v.x; s.y += v.y; s.z += v.z; s.w += v.w;
    }
    ((float4*)out)[b * 2048 + r] = s;
}

// ------------------------------ launch ------------------------------
extern "C" void kernel_launch(void* const* d_in, const int* in_sizes, int n_in,
                              void* d_out, int out_size) {
    const float* H    = (const float*)d_in[0];
    const float* A    = (const float*)d_in[1];
    const float* E    = (const float*)d_in[2];
    const float* Watt = (const float*)d_in[3];
    const float* Wnei = (const float*)d_in[4];
    const float* bAtt = (const float*)d_in[5];
    const float* bNei = (const float*)d_in[6];
    float* out = (float*)d_out;

    cudaFuncSetAttribute(main_kernel, cudaFuncAttributeMaxDynamicSharedMemorySize, SMEM_DYN);

    wprep_kernel<<<104, 256>>>(Watt, Wnei);
    main_kernel<<<Bv * CHUNKS, 256, SMEM_DYN>>>(A, E, H, bAtt, bNei);
    reduce_kernel<<<64, 256>>>(out);
}

// round 8
// speedup vs baseline: 1.8133x; 1.1387x over previous
#include <cuda_runtime.h>
#include <cuda_fp16.h>
#include <cstdint>
#include <cstddef>

#define Bv     8
#define Nv     128
#define FNv    64
#define IPC    8
#define CHUNKS 16

// ------------------------------ device scratch ------------------------------
// fp16 B operand: [n=2l+br (128 rows)][kp (192 perm + pad16)] halves, row = 208 halves.
// k-groups of 16 permuted so lane fragments are one LDS.64.
// ks 0..3 = We rows (W[128+k]), ks 4..7 = Wj rows (W[k]), ks 8..11 = Wi rows (W[k-128]).
__device__ unsigned short g_Wh[128 * 208];
__device__ float g_part[Bv * CHUNKS * Nv * FNv];

// ------------------------------ helpers ------------------------------
__device__ __forceinline__ uint32_t smem_u32(const void* p) {
    uint32_t a;
    asm("{ .reg .u64 t; cvta.to.shared.u64 t, %1; cvt.u32.u64 %0, t; }" : "=r"(a) : "l"(p));
    return a;
}
__device__ __forceinline__ void cp16(uint32_t dst, const void* src) {
    asm volatile("cp.async.cg.shared.global [%0], [%1], 16;" :: "r"(dst), "l"(src) : "memory");
}
__device__ __forceinline__ void cp_commit() {
    asm volatile("cp.async.commit_group;" ::: "memory");
}
template <int N>
__device__ __forceinline__ void cp_wait() {
    asm volatile("cp.async.wait_group %0;" :: "n"(N) : "memory");
}
__device__ __forceinline__ uint32_t packh2(float lo, float hi) {
    uint32_t d; asm("cvt.rn.f16x2.f32 %0, %1, %2;" : "=r"(d) : "f"(hi), "f"(lo)); return d;
}
__device__ __forceinline__ void mma16(float* c, const uint32_t* a, uint32_t b0, uint32_t b1) {
    asm volatile(
        "mma.sync.aligned.m16n8k16.row.col.f32.f16.f16.f32 "
        "{%0,%1,%2,%3}, {%4,%5,%6,%7}, {%8,%9}, {%0,%1,%2,%3};"
        : "+f"(c[0]), "+f"(c[1]), "+f"(c[2]), "+f"(c[3])
        : "r"(a[0]), "r"(a[1]), "r"(a[2]), "r"(a[3]), "r"(b0), "r"(b1));
}
__device__ __forceinline__ double pack2d(float x, float y) {
    double r; asm("mov.b64 %0, {%1, %2};" : "=d"(r) : "f"(x), "f"(y)); return r;
}
__device__ __forceinline__ double add2(double a, double b) {
    double r; asm("add.rn.f32x2 %0, %1, %2;" : "=d"(r) : "d"(a), "d"(b)); return r;
}
__device__ __forceinline__ double fma2v(double a, double b, double c) {
    double r; asm("fma.rn.f32x2 %0, %1, %2, %3;" : "=d"(r) : "d"(a), "d"(b), "d"(c)); return r;
}
__device__ __forceinline__ float2 unpack2d(double v) {
    float2 f; asm("mov.b64 {%0, %1}, %2;" : "=f"(f.x), "=f"(f.y) : "d"(v)); return f;
}

// ------------------------------ weight prep ------------------------------
__global__ void __launch_bounds__(256)
wprep_kernel(const float* __restrict__ Watt, const float* __restrict__ Wnei) {
    const int idx = blockIdx.x * 256 + threadIdx.x;   // < 26624 = 104*256
    const int n = idx / 208, kp = idx % 208;
    const int l = n >> 1, br = n & 1;
    float val = 0.f;
    if (kp < 192) {
        const int ks = kp >> 4, p16 = kp & 15;
        const int k16 = ((p16 >> 2) * 2) + (p16 & 1) + ((p16 >> 1) & 1) * 8;
        const int kglob = ks * 16 + k16;
        int row;
        if (ks < 4)      row = 128 + kglob;     // We
        else if (ks < 8) row = kglob;           // Wj (rows 64..127)
        else             row = kglob - 128;     // Wi (rows 0..63)
        const float* __restrict__ W = br ? Wnei : Watt;
        val = W[row * 64 + l];
    }
    g_Wh[idx] = __half_as_ushort(__float2half_rn(val));
}

// ------------------------------ main kernel ------------------------------
#define OFF_WH  0            // 128 x 416 B = 53248
#define OFF_E16 53248        // 2 x (128 x 160 B) = 40960
#define E16BUF  20480
#define OFF_PJ  94208        // 128 x 68 float2 = 69632
#define PJW     68
#define OFF_PI  163840       // 8 ii x 64 l float2 = 4096
#define OFF_A   167936       // 8 ii x 128 j fp32 = 4096
#define OFF_BS  172032       // 64 float2 (pre-halved) = 512
#define SMEM_DYN 172544

__global__ void __launch_bounds__(256, 1)
main_kernel(const float* __restrict__ A,
            const float* __restrict__ E,
            const float* __restrict__ H,
            const float* __restrict__ biasA,
            const float* __restrict__ biasN) {
    extern __shared__ char sm[];
    const uint32_t sb = smem_u32(sm);

    const int t = threadIdx.x, lane = t & 31, wid = t >> 5;
    const int g = lane >> 2, tg = lane & 3;
    const int b = blockIdx.x >> 4, chunk = blockIdx.x & 15, i0 = chunk * IPC;
    const int mbase = (wid & 3) * 32;
    const int wn    = wid >> 2;
    const int lbase = wn * 32;
    const int nrow0 = wn * 64;

    const uint32_t* __restrict__ Ww = (const uint32_t*)(sm + OFF_WH);

    // ---- async loads: W' + A chunk ----
    {
        #pragma unroll
        for (int v = 0; v < 13; v++)
            cp16(sb + OFF_WH + (v * 256 + t) * 16, (const char*)g_Wh + (v * 256 + t) * 16);
        cp16(sb + OFF_A + t * 16, (const char*)(A + (size_t)(b * Nv + i0) * Nv) + t * 16);
        cp_commit();
    }
    // ---- H tile: LDG -> fp16 permuted STS into E16 buf0 ----
    {
        const float4* Hg = (const float4*)(H + (size_t)b * Nv * FNv);
        float4 hl[8];
        #pragma unroll
        for (int v = 0; v < 8; v++) hl[v] = Hg[v * 256 + t];
        uint32_t* Ebw = (uint32_t*)(sm + OFF_E16);
        #pragma unroll
        for (int v = 0; v < 8; v++) {
            const int n = v * 256 + t, row = n >> 4, kgf = n & 15;
            const int wbase = row * 40 + (kgf >> 2) * 8 + ((kgf & 1) * 4) + ((kgf >> 1) & 1);
            Ebw[wbase]     = packh2(hl[v].x, hl[v].y);
            Ebw[wbase + 2] = packh2(hl[v].z, hl[v].w);
        }
    }
    if (t < 64)
        ((float2*)(sm + OFF_BS))[t] =
            make_float2(0.5f * __ldg(biasA + t), 0.5f * __ldg(biasN + t));
    cp_wait<0>();
    __syncthreads();          // W + A + H-tile resident

    // ---- prologue GEMM: Pj (ks 4..7) and Pi (ks 8..11) from H ----
    {
        const uint32_t* __restrict__ Ew = (const uint32_t*)(sm + OFF_E16);
        float cpj[2][8][4], cpi[2][8][4];
        #pragma unroll
        for (int mt = 0; mt < 2; mt++)
            #pragma unroll
            for (int nt = 0; nt < 8; nt++)
                #pragma unroll
                for (int q = 0; q < 4; q++) { cpj[mt][nt][q] = 0.f; cpi[mt][nt][q] = 0.f; }

        #pragma unroll
        for (int ks = 0; ks < 4; ks++) {
            uint32_t a[2][4];
            #pragma unroll
            for (int mt = 0; mt < 2; mt++) {
                const int r = mbase + mt * 16 + g;
                const uint2 u0 = *(const uint2*)(Ew + r * 40 + ks * 8 + tg * 2);
                const uint2 u1 = *(const uint2*)(Ew + (r + 8) * 40 + ks * 8 + tg * 2);
                a[mt][0] = u0.x; a[mt][1] = u1.x; a[mt][2] = u0.y; a[mt][3] = u1.y;
            }
            #pragma unroll
            for (int nt = 0; nt < 8; nt++) {
                const int nr = (nrow0 + nt * 8 + g) * 104;
                const uint2 bj = *(const uint2*)(Ww + nr + (ks + 4) * 8 + tg * 2);
                const uint2 bi = *(const uint2*)(Ww + nr + (ks + 8) * 8 + tg * 2);
                mma16(cpj[0][nt], a[0], bj.x, bj.y);
                mma16(cpj[1][nt], a[1], bj.x, bj.y);
                mma16(cpi[0][nt], a[0], bi.x, bi.y);
                mma16(cpi[1][nt], a[1], bi.x, bi.y);
            }
        }
        // scatter Pj (all threads)
        float2* __restrict__ PJ = (float2*)(sm + OFF_PJ);
        #pragma unroll
        for (int mt = 0; mt < 2; mt++) {
            const int j0 = mbase + mt * 16 + g;
            #pragma unroll
            for (int nt = 0; nt < 8; nt++) {
                const int l = lbase + nt * 4 + tg;
                PJ[(size_t)j0 * PJW + l]       = make_float2(cpj[mt][nt][0], cpj[mt][nt][1]);
                PJ[(size_t)(j0 + 8) * PJW + l] = make_float2(cpj[mt][nt][2], cpj[mt][nt][3]);
            }
        }
        // scatter Pi (owning warp group only): rows i0..i0+7
        if ((wid & 3) == ((i0 >> 5) & 3)) {
            const int mtv = (i0 >> 4) & 1, hsv = (i0 >> 3) & 1;
            float2* __restrict__ Pis = (float2*)(sm + OFF_PI);
            #pragma unroll
            for (int nt = 0; nt < 8; nt++) {
                float va, vn;
                if (mtv == 0) {
                    if (hsv == 0) { va = cpi[0][nt][0]; vn = cpi[0][nt][1]; }
                    else          { va = cpi[0][nt][2]; vn = cpi[0][nt][3]; }
                } else {
                    if (hsv == 0) { va = cpi[1][nt][0]; vn = cpi[1][nt][1]; }
                    else          { va = cpi[1][nt][2]; vn = cpi[1][nt][3]; }
                }
                Pis[g * 64 + lbase + nt * 4 + tg] = make_float2(va, vn);
            }
        }
    }

    // ---- hoist B fragments (We, ks 0..3) into registers: loop-invariant ----
    uint2 Breg[4][8];
    #pragma unroll
    for (int ks = 0; ks < 4; ks++)
        #pragma unroll
        for (int nt = 0; nt < 8; nt++)
            Breg[ks][nt] = *(const uint2*)(Ww + (nrow0 + nt * 8 + g) * 104 + ks * 8 + tg * 2);

    // ---- prefetch E tile 0 ----
    float4 el[8];
    {
        const float4* Eg = (const float4*)(E + ((size_t)(b * Nv + i0)) * Nv * FNv);
        #pragma unroll
        for (int v = 0; v < 8; v++) el[v] = Eg[v * 256 + t];
    }
    __syncthreads();          // Pj/Pi visible; H-tile reads done -> buf0 reusable

    float outacc[2][2][8];
    #pragma unroll
    for (int mt = 0; mt < 2; mt++)
        #pragma unroll
        for (int h = 0; h < 2; h++)
            #pragma unroll
            for (int nt = 0; nt < 8; nt++) outacc[mt][h][nt] = 0.f;

    for (int ii = 0; ii < IPC; ii++) {
        // ---- convert + store tile ii ----
        {
            uint32_t* Ebw = (uint32_t*)(sm + OFF_E16 + (ii & 1) * E16BUF);
            #pragma unroll
            for (int v = 0; v < 8; v++) {
                const int n = v * 256 + t, row = n >> 4, kgf = n & 15;
                const int wbase = row * 40 + (kgf >> 2) * 8 + ((kgf & 1) * 4) + ((kgf >> 1) & 1);
                Ebw[wbase]     = packh2(el[v].x, el[v].y);
                Ebw[wbase + 2] = packh2(el[v].z, el[v].w);
            }
        }
        __syncthreads();

        // ---- prefetch tile ii+1 (lands during GEMM) ----
        if (ii + 1 < IPC) {
            const float4* Eg = (const float4*)(E + ((size_t)(b * Nv + i0 + ii + 1)) * Nv * FNv);
            #pragma unroll
            for (int v = 0; v < 8; v++) el[v] = Eg[v * 256 + t];
        }

        // ---- GEMM (B from registers) ----
        const uint32_t* __restrict__ Ew = (const uint32_t*)(sm + OFF_E16 + (ii & 1) * E16BUF);
        float c[2][8][4];
        #pragma unroll
        for (int mt = 0; mt < 2; mt++)
            #pragma unroll
            for (int nt = 0; nt < 8; nt++)
                #pragma unroll
                for (int q = 0; q < 4; q++) c[mt][nt][q] = 0.f;

        #pragma unroll
        for (int ks = 0; ks < 4; ks++) {
            uint32_t a[2][4];
            #pragma unroll
            for (int mt = 0; mt < 2; mt++) {
                const int r = mbase + mt * 16 + g;
                const uint2 u0 = *(const uint2*)(Ew + r * 40 + ks * 8 + tg * 2);
                const uint2 u1 = *(const uint2*)(Ew + (r + 8) * 40 + ks * 8 + tg * 2);
                a[mt][0] = u0.x; a[mt][1] = u1.x; a[mt][2] = u0.y; a[mt][3] = u1.y;
            }
            #pragma unroll
            for (int nt = 0; nt < 8; nt++) {
                mma16(c[0][nt], a[0], Breg[ks][nt].x, Breg[ks][nt].y);
                mma16(c[1][nt], a[1], Breg[ks][nt].x, Breg[ks][nt].y);
            }
        }

        // ---- epilogue (f32x2 packed, pre-halved scales) ----
        const float*  __restrict__ As  = (const float*)(sm + OFF_A) + ii * 128;
        const double* __restrict__ Pid = (const double*)(sm + OFF_PI) + ii * 64;
        const double* __restrict__ Bsd = (const double*)(sm + OFF_BS);
        const double* __restrict__ PJd = (const double*)(sm + OFF_PJ);

        #pragma unroll
        for (int mt = 0; mt < 2; mt++) {
            const int j0 = mbase + mt * 16 + g;
            const float ah0 = 0.5f * As[j0], ah1 = 0.5f * As[j0 + 8];
            const double a2_0 = pack2d(ah0, ah0);
            const double a2_1 = pack2d(ah1, ah1);
            const double* pr0 = PJd + (size_t)j0 * PJW;
            const double* pr1 = PJd + (size_t)(j0 + 8) * PJW;
            #pragma unroll
            for (int nt = 0; nt < 8; nt++) {
                const int l = lbase + nt * 4 + tg;
                const double pi2 = Pid[l];
                const double bs2 = Bsd[l];
                {
                    const double d2 = pack2d(c[mt][nt][0], c[mt][nt][1]);
                    const double s2 = add2(add2(d2, pi2), pr0[l]);
                    const float2 r  = unpack2d(fma2v(a2_0, s2, bs2));
                    float th; asm("tanh.approx.f32 %0, %1;" : "=f"(th) : "f"(r.x));
                    outacc[mt][0][nt] = fmaf(fmaxf(r.y, 0.f), fmaf(0.5f, th, 0.5f),
                                             outacc[mt][0][nt]);
                }
                {
                    const double d2 = pack2d(c[mt][nt][2], c[mt][nt][3]);
                    const double s2 = add2(add2(d2, pi2), pr1[l]);
                    const float2 r  = unpack2d(fma2v(a2_1, s2, bs2));
                    float th; asm("tanh.approx.f32 %0, %1;" : "=f"(th) : "f"(r.x));
                    outacc[mt][1][nt] = fmaf(fmaxf(r.y, 0.f), fmaf(0.5f, th, 0.5f),
                                             outacc[mt][1][nt]);
                }
            }
        }
    }

    // ---- store partials (x0.5 scale; compensated in reduce) ----
    float* __restrict__ dst = g_part + (size_t)blockIdx.x * Nv * FNv;
    #pragma unroll
    for (int mt = 0; mt < 2; mt++)
        #pragma unroll
        for (int h = 0; h < 2; h++) {
            const int j = mbase + mt * 16 + h * 8 + g;
            #pragma unroll
            for (int nt = 0; nt < 8; nt++)
                dst[(size_t)j * FNv + lbase + nt * 4 + tg] = outacc[mt][h][nt];
        }
}

// ------------------------------ reduce kernel ------------------------------
__global__ void __launch_bounds__(256)
reduce_kernel(float* __restrict__ out) {
    const int f4 = blockIdx.x * 256 + threadIdx.x;
    const int b = f4 >> 11;
    const int r = f4 & 2047;
    const float4* P = (const float4*)g_part;
    float4 s = make_float4(0.f, 0.f, 0.f, 0.f);
    #pragma unroll
    for (int c = 0; c < CHUNKS; c++) {
        const float4 v = P[((size_t)(b * CHUNKS + c)) * 2048 + r];
        s.x += v.x; s.y += v.y; s.z += v.z; s.w += v.w;
    }
    s.x *= 2.f; s.y *= 2.f; s.z *= 2.f; s.w *= 2.f;   // undo pre-halving
    ((float4*)out)[b * 2048 + r] = s;
}

// ------------------------------ launch ------------------------------
extern "C" void kernel_launch(void* const* d_in, const int* in_sizes, int n_in,
                              void* d_out, int out_size) {
    const float* H    = (const float*)d_in[0];
    const float* A    = (const float*)d_in[1];
    const float* E    = (const float*)d_in[2];
    const float* Watt = (const float*)d_in[3];
    const float* Wnei = (const float*)d_in[4];
    const float* bAtt = (const float*)d_in[5];
    const float* bNei = (const float*)d_in[6];
    float* out = (float*)d_out;

    cudaFuncSetAttribute(main_kernel, cudaFuncAttributeMaxDynamicSharedMemorySize, SMEM_DYN);

    wprep_kernel<<<104, 256>>>(Watt, Wnei);
    main_kernel<<<Bv * CHUNKS, 256, SMEM_DYN>>>(A, E, H, bAtt, bNei);
    reduce_kernel<<<64, 256>>>(out);
}

// round 9
// speedup vs baseline: 2.0482x; 1.1295x over previous
#include <cuda_runtime.h>
#include <cuda_fp16.h>
#include <cstdint>
#include <cstddef>

#define Bv     8
#define Nv     128
#define FNv    64

// ------------------------------ device scratch ------------------------------
// fp16 B operand: [n=2l+br (128 rows)][kp (192 perm + pad16)] halves, row = 208 halves.
// ks 0..3 = We rows (W[128+k]), ks 4..7 = Wj rows (W[k]), ks 8..11 = Wi rows (W[k-128]).
__device__ unsigned short g_Wh[128 * 208];

// ------------------------------ helpers ------------------------------
__device__ __forceinline__ uint32_t smem_u32(const void* p) {
    uint32_t a;
    asm("{ .reg .u64 t; cvta.to.shared.u64 t, %1; cvt.u32.u64 %0, t; }" : "=r"(a) : "l"(p));
    return a;
}
__device__ __forceinline__ void cp16(uint32_t dst, const void* src) {
    asm volatile("cp.async.cg.shared.global [%0], [%1], 16;" :: "r"(dst), "l"(src) : "memory");
}
__device__ __forceinline__ void cp_commit() {
    asm volatile("cp.async.commit_group;" ::: "memory");
}
template <int N>
__device__ __forceinline__ void cp_wait() {
    asm volatile("cp.async.wait_group %0;" :: "n"(N) : "memory");
}
__device__ __forceinline__ uint32_t packh2(float lo, float hi) {
    uint32_t d; asm("cvt.rn.f16x2.f32 %0, %1, %2;" : "=r"(d) : "f"(hi), "f"(lo)); return d;
}
__device__ __forceinline__ void mma16(float* c, const uint32_t* a, uint32_t b0, uint32_t b1) {
    asm volatile(
        "mma.sync.aligned.m16n8k16.row.col.f32.f16.f16.f32 "
        "{%0,%1,%2,%3}, {%4,%5,%6,%7}, {%8,%9}, {%0,%1,%2,%3};"
        : "+f"(c[0]), "+f"(c[1]), "+f"(c[2]), "+f"(c[3])
        : "r"(a[0]), "r"(a[1]), "r"(a[2]), "r"(a[3]), "r"(b0), "r"(b1));
}
__device__ __forceinline__ double pack2d(float x, float y) {
    double r; asm("mov.b64 %0, {%1, %2};" : "=d"(r) : "f"(x), "f"(y)); return r;
}
__device__ __forceinline__ double add2(double a, double b) {
    double r; asm("add.rn.f32x2 %0, %1, %2;" : "=d"(r) : "d"(a), "d"(b)); return r;
}
__device__ __forceinline__ double fma2v(double a, double b, double c) {
    double r; asm("fma.rn.f32x2 %0, %1, %2, %3;" : "=d"(r) : "d"(a), "d"(b), "d"(c)); return r;
}
__device__ __forceinline__ float2 unpack2d(double v) {
    float2 f; asm("mov.b64 {%0, %1}, %2;" : "=f"(f.x), "=f"(f.y) : "d"(v)); return f;
}

// ------------------------------ weight prep ------------------------------
__global__ void __launch_bounds__(256)
wprep_kernel(const float* __restrict__ Watt, const float* __restrict__ Wnei) {
    const int idx = blockIdx.x * 256 + threadIdx.x;   // < 26624 = 104*256
    const int n = idx / 208, kp = idx % 208;
    const int l = n >> 1, br = n & 1;
    float val = 0.f;
    if (kp < 192) {
        const int ks = kp >> 4, p16 = kp & 15;
        const int k16 = ((p16 >> 2) * 2) + (p16 & 1) + ((p16 >> 1) & 1) * 8;
        const int kglob = ks * 16 + k16;
        int row;
        if (ks < 4)      row = 128 + kglob;     // We
        else if (ks < 8) row = kglob;           // Wj (rows 64..127)
        else             row = kglob - 128;     // Wi (rows 0..63)
        const float* __restrict__ W = br ? Wnei : Watt;
        val = W[row * 64 + l];
    }
    g_Wh[idx] = __half_as_ushort(__float2half_rn(val));
}

// ------------------------------ main kernel ------------------------------
// CTA = (b, j-block of 8). Iterates i in 8 tiles of 16. Tile row r = il*8 + jl.
#define OFF_WH  0            // 128 x 416 B = 53248
#define OFF_E16 53248        // 2 x 20480 = 40960
#define E16BUF  20480
#define OFF_PI  94208        // 128 i x 66 float2 = 67584
#define PIW     66
#define OFF_PJ  161792       // 8 j x 66 float2 = 4224
#define OFF_A   166016       // 128 i x 8 j fp32 = 4096
#define OFF_BS  170112       // 64 float2 (pre-halved) = 512
#define SMEM_DYN 170624

__global__ void __launch_bounds__(256, 1)
main_kernel(const float* __restrict__ A,
            const float* __restrict__ E,
            const float* __restrict__ H,
            const float* __restrict__ biasA,
            const float* __restrict__ biasN,
            float* __restrict__ out) {
    extern __shared__ char sm[];
    const uint32_t sb = smem_u32(sm);

    const int t = threadIdx.x, lane = t & 31, wid = t >> 5;
    const int g = lane >> 2, tg = lane & 3;
    const int b = blockIdx.x >> 4, jb = blockIdx.x & 15;
    const int wm = wid & 3;                     // m-quadrant (i-groups)
    const int wn = wid >> 2;                    // l-half
    const int mbase = wm * 32;
    const int lbase = wn * 32;
    const int nrow0 = wn * 64;

    const uint32_t* __restrict__ Ww = (const uint32_t*)(sm + OFF_WH);

    // ---- async loads: W' + A block ----
    {
        #pragma unroll
        for (int v = 0; v < 13; v++)
            cp16(sb + OFF_WH + (v * 256 + t) * 16, (const char*)g_Wh + (v * 256 + t) * 16);
        // A[b, i, jb*8 .. +8): 32 B per i, 2 cp16 -> t: i = t>>1, half = t&1
        const int ia = t >> 1, ha = t & 1;
        cp16(sb + OFF_A + ia * 32 + ha * 16,
             (const char*)(A + ((size_t)(b * Nv + ia)) * Nv + jb * 8) + ha * 16);
        cp_commit();
    }
    // ---- H tile: LDG -> fp16 permuted STS into E16 buf0 ----
    {
        const float4* Hg = (const float4*)(H + (size_t)b * Nv * FNv);
        float4 hl[8];
        #pragma unroll
        for (int v = 0; v < 8; v++) hl[v] = Hg[v * 256 + t];
        uint32_t* Ebw = (uint32_t*)(sm + OFF_E16);
        #pragma unroll
        for (int v = 0; v < 8; v++) {
            const int n = v * 256 + t, row = n >> 4, kgf = n & 15;
            const int wbase = row * 40 + (kgf >> 2) * 8 + ((kgf & 1) * 4) + ((kgf >> 1) & 1);
            Ebw[wbase]     = packh2(hl[v].x, hl[v].y);
            Ebw[wbase + 2] = packh2(hl[v].z, hl[v].w);
        }
    }
    if (t < 64)
        ((float2*)(sm + OFF_BS))[t] =
            make_float2(0.5f * __ldg(biasA + t), 0.5f * __ldg(biasN + t));
    cp_wait<0>();
    __syncthreads();          // W + A + H-tile resident

    // ---- prologue GEMM: Pi (ks 8..11, all 128 nodes) and Pj (ks 4..7, 8 nodes) ----
    {
        const uint32_t* __restrict__ Ew = (const uint32_t*)(sm + OFF_E16);
        float cpj[2][8][4], cpi[2][8][4];
        #pragma unroll
        for (int mt = 0; mt < 2; mt++)
            #pragma unroll
            for (int nt = 0; nt < 8; nt++)
                #pragma unroll
                for (int q = 0; q < 4; q++) { cpj[mt][nt][q] = 0.f; cpi[mt][nt][q] = 0.f; }

        #pragma unroll
        for (int ks = 0; ks < 4; ks++) {
            uint32_t a[2][4];
            #pragma unroll
            for (int mt = 0; mt < 2; mt++) {
                const int r = mbase + mt * 16 + g;
                const uint2 u0 = *(const uint2*)(Ew + r * 40 + ks * 8 + tg * 2);
                const uint2 u1 = *(const uint2*)(Ew + (r + 8) * 40 + ks * 8 + tg * 2);
                a[mt][0] = u0.x; a[mt][1] = u1.x; a[mt][2] = u0.y; a[mt][3] = u1.y;
            }
            #pragma unroll
            for (int nt = 0; nt < 8; nt++) {
                const int nr = (nrow0 + nt * 8 + g) * 104;
                const uint2 bj = *(const uint2*)(Ww + nr + (ks + 4) * 8 + tg * 2);
                const uint2 bi = *(const uint2*)(Ww + nr + (ks + 8) * 8 + tg * 2);
                mma16(cpj[0][nt], a[0], bj.x, bj.y);
                mma16(cpj[1][nt], a[1], bj.x, bj.y);
                mma16(cpi[0][nt], a[0], bi.x, bi.y);
                mma16(cpi[1][nt], a[1], bi.x, bi.y);
            }
        }
        // scatter Pi (all 128 rows)
        float2* __restrict__ PIs = (float2*)(sm + OFF_PI);
        #pragma unroll
        for (int mt = 0; mt < 2; mt++) {
            const int r0 = mbase + mt * 16 + g;
            #pragma unroll
            for (int nt = 0; nt < 8; nt++) {
                const int l = lbase + nt * 4 + tg;
                PIs[(size_t)r0 * PIW + l]       = make_float2(cpi[mt][nt][0], cpi[mt][nt][1]);
                PIs[(size_t)(r0 + 8) * PIW + l] = make_float2(cpi[mt][nt][2], cpi[mt][nt][3]);
            }
        }
        // scatter Pj window (rows jb*8 .. +8): owning (wm, mt, h) combo
        float2* __restrict__ PJs = (float2*)(sm + OFF_PJ);
        #pragma unroll
        for (int mt = 0; mt < 2; mt++) {
            #pragma unroll
            for (int h = 0; h < 2; h++) {
                if (wm * 4 + mt * 2 + h == (jb >> 2) * 4 + (jb & 3)) {   // == jb
                    #pragma unroll
                    for (int nt = 0; nt < 8; nt++) {
                        const int l = lbase + nt * 4 + tg;
                        const float va = cpj[mt][nt][h * 2];
                        const float vn = cpj[mt][nt][h * 2 + 1];
                        PJs[(size_t)g * PIW + l] = make_float2(va, vn);
                    }
                }
            }
        }
    }

    // ---- hoist B fragments (We, ks 0..3) into registers ----
    uint2 Breg[4][8];
    #pragma unroll
    for (int ks = 0; ks < 4; ks++)
        #pragma unroll
        for (int nt = 0; nt < 8; nt++)
            Breg[ks][nt] = *(const uint2*)(Ww + (nrow0 + nt * 8 + g) * 104 + ks * 8 + tg * 2);

    // ---- prefetch E tile 0 (rows r = il*8+jl, i = r>>3, j = jb*8 + (r&7)) ----
    float4 el[8];
    {
        #pragma unroll
        for (int v = 0; v < 8; v++) {
            const int n = v * 256 + t, row = n >> 4, kgf = n & 15;
            const float4* p = (const float4*)
                (E + (((size_t)(b * Nv + (row >> 3)) * Nv) + jb * 8 + (row & 7)) * FNv) + kgf;
            el[v] = *p;
        }
    }
    __syncthreads();          // Pi/Pj visible; H reads done -> buf0 reusable

    // ---- Pj into registers (j = g fixed per thread) ----
    double pj2[8];
    {
        const double* __restrict__ PJd = (const double*)(sm + OFF_PJ);
        #pragma unroll
        for (int nt = 0; nt < 8; nt++)
            pj2[nt] = PJd[(size_t)g * PIW + lbase + nt * 4 + tg];
    }

    float outacc[8];
    #pragma unroll
    for (int nt = 0; nt < 8; nt++) outacc[nt] = 0.f;

    for (int ii = 0; ii < 8; ii++) {
        // ---- convert + store tile ii ----
        {
            uint32_t* Ebw = (uint32_t*)(sm + OFF_E16 + (ii & 1) * E16BUF);
            #pragma unroll
            for (int v = 0; v < 8; v++) {
                const int n = v * 256 + t, row = n >> 4, kgf = n & 15;
                const int wbase = row * 40 + (kgf >> 2) * 8 + ((kgf & 1) * 4) + ((kgf >> 1) & 1);
                Ebw[wbase]     = packh2(el[v].x, el[v].y);
                Ebw[wbase + 2] = packh2(el[v].z, el[v].w);
            }
        }
        __syncthreads();

        // ---- prefetch tile ii+1 ----
        if (ii + 1 < 8) {
            #pragma unroll
            for (int v = 0; v < 8; v++) {
                const int n = v * 256 + t, row = n >> 4, kgf = n & 15;
                const float4* p = (const float4*)
                    (E + (((size_t)(b * Nv + (ii + 1) * 16 + (row >> 3)) * Nv)
                          + jb * 8 + (row & 7)) * FNv) + kgf;
                el[v] = *p;
            }
        }

        // ---- GEMM ----
        const uint32_t* __restrict__ Ew = (const uint32_t*)(sm + OFF_E16 + (ii & 1) * E16BUF);
        float c[2][8][4];
        #pragma unroll
        for (int mt = 0; mt < 2; mt++)
            #pragma unroll
            for (int nt = 0; nt < 8; nt++)
                #pragma unroll
                for (int q = 0; q < 4; q++) c[mt][nt][q] = 0.f;

        #pragma unroll
        for (int ks = 0; ks < 4; ks++) {
            uint32_t a[2][4];
            #pragma unroll
            for (int mt = 0; mt < 2; mt++) {
                const int r = mbase + mt * 16 + g;
                const uint2 u0 = *(const uint2*)(Ew + r * 40 + ks * 8 + tg * 2);
                const uint2 u1 = *(const uint2*)(Ew + (r + 8) * 40 + ks * 8 + tg * 2);
                a[mt][0] = u0.x; a[mt][1] = u1.x; a[mt][2] = u0.y; a[mt][3] = u1.y;
            }
            #pragma unroll
            for (int nt = 0; nt < 8; nt++) {
                mma16(c[0][nt], a[0], Breg[ks][nt].x, Breg[ks][nt].y);
                mma16(c[1][nt], a[1], Breg[ks][nt].x, Breg[ks][nt].y);
            }
        }

        // ---- epilogue: gate + i-accumulate (all rows share j = jb*8+g) ----
        const float*  __restrict__ As  = (const float*)(sm + OFF_A);
        const double* __restrict__ Pid = (const double*)(sm + OFF_PI);
        const double* __restrict__ Bsd = (const double*)(sm + OFF_BS);

        #pragma unroll
        for (int mt = 0; mt < 2; mt++) {
            #pragma unroll
            for (int h = 0; h < 2; h++) {
                const int il = wm * 4 + mt * 2 + h;
                const int i  = ii * 16 + il;
                const float ah = 0.5f * As[i * 8 + g];
                const double a2 = pack2d(ah, ah);
                const double* pir = Pid + (size_t)i * PIW;
                #pragma unroll
                for (int nt = 0; nt < 8; nt++) {
                    const int l = lbase + nt * 4 + tg;
                    const double d2 = pack2d(c[mt][nt][h * 2], c[mt][nt][h * 2 + 1]);
                    const double s2 = add2(add2(d2, pir[l]), pj2[nt]);
                    const float2 r  = unpack2d(fma2v(a2, s2, Bsd[l]));
                    float th; asm("tanh.approx.f32 %0, %1;" : "=f"(th) : "f"(r.x));
                    outacc[nt] = fmaf(fmaxf(r.y, 0.f), fmaf(0.5f, th, 0.5f), outacc[nt]);
                }
            }
        }
    }

    // ---- cross-warp (wm) reduction + store ----
    __syncthreads();
    float* __restrict__ Sred = (float*)(sm + OFF_E16);   // [wm][wn][g][32] = 2048 floats
    #pragma unroll
    for (int nt = 0; nt < 8; nt++)
        Sred[(((wm * 2 + wn) * 8 + g) * 32) + nt * 4 + tg] = outacc[nt];
    __syncthreads();

    {
        const int o = t * 2;                    // 512 outputs: j = o>>6, l = o&63
        const int j = o >> 6, l = o & 63;
        const int wnn = l >> 5, lloc = l & 31;
        float s0 = 0.f, s1 = 0.f;
        #pragma unroll
        for (int w = 0; w < 4; w++) {
            s0 += Sred[((w * 2 + wnn) * 8 + j) * 32 + lloc];
            s1 += Sred[((w * 2 + wnn) * 8 + j) * 32 + lloc + 1];
        }
        float2 v = make_float2(2.f * s0, 2.f * s1);       // undo pre-halving
        *(float2*)(out + ((size_t)(b * Nv) + jb * 8 + j) * FNv + l) = v;
    }
}

// ------------------------------ launch ------------------------------
extern "C" void kernel_launch(void* const* d_in, const int* in_sizes, int n_in,
                              void* d_out, int out_size) {
    const float* H    = (const float*)d_in[0];
    const float* A    = (const float*)d_in[1];
    const float* E    = (const float*)d_in[2];
    const float* Watt = (const float*)d_in[3];
    const float* Wnei = (const float*)d_in[4];
    const float* bAtt = (const float*)d_in[5];
    const float* bNei = (const float*)d_in[6];
    float* out = (float*)d_out;

    cudaFuncSetAttribute(main_kernel, cudaFuncAttributeMaxDynamicSharedMemorySize, SMEM_DYN);

    wprep_kernel<<<104, 256>>>(Watt, Wnei);
    main_kernel<<<Bv * 16, 256, SMEM_DYN>>>(A, E, H, bAtt, bNei, out);
}